// round 1
// baseline (speedup 1.0000x reference)
#include <cuda_runtime.h>
#include <cuda_bf16.h>
#include <cstdint>

#define VOCAB 50257
#define EMB   16
#define BS    8
#define MCW   512
#define NROW  (BS * MCW)   // 4096

// ---------------- scratch (static device globals; no allocs) ----------------
__device__ float g_q[NROW * EMB];
__device__ float g_k[NROW * EMB];
__device__ float g_v[NROW * EMB];
__device__ float g_sc[BS * MCW * MCW];     // stored TRANSPOSED: [b][k][q]  (8 MB)
__device__ float g_out_t[EMB * NROW];      // transposed attention output: [e][r]

__device__ __forceinline__ unsigned long long pack2(float lo, float hi) {
    unsigned long long r;
    asm("mov.b64 %0, {%1, %2};" : "=l"(r) : "f"(lo), "f"(hi));
    return r;
}
__device__ __forceinline__ void unpack2(unsigned long long p, float& lo, float& hi) {
    asm("mov.b64 {%0, %1}, %2;" : "=f"(lo), "=f"(hi) : "l"(p));
}

// ---------------- Kernel A: embeddings -> Q, K, V ----------------
__global__ void qkv_kernel(const int* __restrict__ x,
                           const float* __restrict__ emb_table,
                           const float* __restrict__ Wq, const float* __restrict__ bq,
                           const float* __restrict__ Wk, const float* __restrict__ bk,
                           const float* __restrict__ Wv, const float* __restrict__ bv) {
    __shared__ float sWq[EMB * EMB], sWk[EMB * EMB], sWv[EMB * EMB];
    __shared__ float sbq[EMB], sbk[EMB], sbv[EMB];
    int tid = threadIdx.x;
    if (tid < EMB * EMB) { sWq[tid] = Wq[tid]; sWk[tid] = Wk[tid]; sWv[tid] = Wv[tid]; }
    if (tid < EMB)       { sbq[tid] = bq[tid]; sbk[tid] = bk[tid]; sbv[tid] = bv[tid]; }
    __syncthreads();

    int t = blockIdx.x * blockDim.x + tid;   // 0..4095
    if (t >= NROW) return;
    int tok = x[t];

    float emb[EMB];
    const float4* ep = reinterpret_cast<const float4*>(emb_table + (size_t)tok * EMB);
#pragma unroll
    for (int i = 0; i < 4; i++) {
        float4 v4 = ep[i];
        emb[4 * i + 0] = v4.x; emb[4 * i + 1] = v4.y;
        emb[4 * i + 2] = v4.z; emb[4 * i + 3] = v4.w;
    }

#pragma unroll
    for (int i = 0; i < EMB; i++) {
        float aq = sbq[i], ak = sbk[i], av = sbv[i];
#pragma unroll
        for (int e = 0; e < EMB; e++) {
            aq += emb[e] * sWq[i * EMB + e];
            ak += emb[e] * sWk[i * EMB + e];
            av += emb[e] * sWv[i * EMB + e];
        }
        g_q[t * EMB + i] = aq;
        g_k[t * EMB + i] = ak;
        g_v[t * EMB + i] = av;
    }
}

// ---------------- Kernel B: scores (masked, zero->-inf), stored [b][k][q] ----------------
__global__ void scores_kernel() {
    // grid (32, 32, 8), block (16, 16): tx = q_local, ty = k_local
    __shared__ float sQ[16][17];
    __shared__ float sK[16][17];
    int b = blockIdx.z;
    int qbase = blockIdx.x * 16;
    int kbase = blockIdx.y * 16;
    int tx = threadIdx.x, ty = threadIdx.y;

    sQ[ty][tx] = g_q[((size_t)(b * MCW + qbase + ty)) * EMB + tx];
    sK[ty][tx] = g_k[((size_t)(b * MCW + kbase + ty)) * EMB + tx];
    __syncthreads();

    int q = qbase + tx;
    int k = kbase + ty;
    float dot = 0.f;
#pragma unroll
    for (int e = 0; e < EMB; e++) dot += sQ[tx][e] * sK[ty][e];

    float val = (k <= q) ? dot : 0.0f;
    if (val == 0.0f) val = __int_as_float(0xff800000);  // -inf (also catches exact zeros)
    g_sc[(size_t)b * MCW * MCW + (size_t)k * MCW + q] = val;
}

// ---------------- Kernel C: softmax over q (rows of the transposed scores) ----------------
__global__ void softmax_kernel() {
    int warp = threadIdx.x >> 5, lane = threadIdx.x & 31;
    int row = blockIdx.x * 8 + warp;          // row = b*512 + k, 0..4095
    float* p = g_sc + (size_t)row * MCW;

    float v[16];
    float mx = -3.402823466e+38f;
#pragma unroll
    for (int j = 0; j < 16; j++) { v[j] = p[j * 32 + lane]; mx = fmaxf(mx, v[j]); }
#pragma unroll
    for (int s = 16; s > 0; s >>= 1) mx = fmaxf(mx, __shfl_xor_sync(0xffffffffu, mx, s));

    float sum = 0.f;
#pragma unroll
    for (int j = 0; j < 16; j++) { v[j] = expf(v[j] - mx); sum += v[j]; }
#pragma unroll
    for (int s = 16; s > 0; s >>= 1) sum += __shfl_xor_sync(0xffffffffu, sum, s);

    float inv = 1.0f / sum;
#pragma unroll
    for (int j = 0; j < 16; j++) p[j * 32 + lane] = v[j] * inv;
}

// ---------------- Kernel D: out[b,w,e] = sum_p weights[b,w,p] * V[b,p,e] ----------------
__global__ void attnout_kernel() {
    // grid (16, 8): x = w-tile (32 w's), y = b.  block (32, 8): tx = w_local, ty = p-group
    __shared__ float sV[MCW * EMB];   // 32 KB; reused as reduction buffer afterwards
    int b = blockIdx.y;
    int w0 = blockIdx.x * 32;
    int wl = threadIdx.x, pg = threadIdx.y;
    int tid = pg * 32 + wl;

    for (int i = tid; i < MCW * EMB; i += 256)
        sV[i] = g_v[(size_t)b * MCW * EMB + i];
    __syncthreads();

    float acc[EMB];
#pragma unroll
    for (int e = 0; e < EMB; e++) acc[e] = 0.f;

    const float* wbase = g_sc + (size_t)b * MCW * MCW + w0 + wl;
    for (int p = pg; p < MCW; p += 8) {
        float wgt = wbase[(size_t)p * MCW];
#pragma unroll
        for (int e = 0; e < EMB; e++) acc[e] += wgt * sV[p * EMB + e];
    }
    __syncthreads();   // everyone done reading sV; reuse it for the reduction

#pragma unroll
    for (int e = 0; e < EMB; e++) sV[(pg * 32 + wl) * EMB + e] = acc[e];
    __syncthreads();

    if (pg == 0) {
#pragma unroll
        for (int e = 0; e < EMB; e++) {
            float s = 0.f;
#pragma unroll
            for (int g = 0; g < 8; g++) s += sV[(g * 32 + wl) * EMB + e];
            g_out_t[(size_t)e * NROW + b * MCW + w0 + wl] = s;
        }
    }
}

// ---------------- Kernel E: logits = out @ Wl.T + bl  (the 823 MB write) ----------------
// f32x2-packed: each thread owns 2 vocab ids (v0 = base+tid, v1 = v0+256), f32x2 lanes
// are paired over ROWS so the Wl replicate-pack is loop-invariant.
#define E_RT 128
__global__ __launch_bounds__(256) void logits_kernel(const float* __restrict__ Wl,
                                                     const float* __restrict__ bl,
                                                     float* __restrict__ out) {
    __shared__ float s[EMB * E_RT];   // transposed out tile: s[e][r_local], 8 KB
    int tid = threadIdx.x;
    int v0 = blockIdx.x * 512 + tid;
    int v1 = v0 + 256;
    int rbase = blockIdx.y * E_RT;

    for (int i = tid; i < EMB * E_RT; i += 256) {
        int e = i >> 7, rl = i & (E_RT - 1);
        s[i] = g_out_t[(size_t)e * NROW + rbase + rl];
    }

    unsigned long long w0[EMB], w1[EMB], b0 = 0ull, b1 = 0ull;
    bool ok0 = (v0 < VOCAB), ok1 = (v1 < VOCAB);
    if (ok0) {
        const float4* wp = reinterpret_cast<const float4*>(Wl + (size_t)v0 * EMB);
#pragma unroll
        for (int i = 0; i < 4; i++) {
            float4 q = wp[i];
            w0[4 * i + 0] = pack2(q.x, q.x); w0[4 * i + 1] = pack2(q.y, q.y);
            w0[4 * i + 2] = pack2(q.z, q.z); w0[4 * i + 3] = pack2(q.w, q.w);
        }
        float bb = bl[v0]; b0 = pack2(bb, bb);
    } else {
#pragma unroll
        for (int e = 0; e < EMB; e++) w0[e] = 0ull;
    }
    if (ok1) {
        const float4* wp = reinterpret_cast<const float4*>(Wl + (size_t)v1 * EMB);
#pragma unroll
        for (int i = 0; i < 4; i++) {
            float4 q = wp[i];
            w1[4 * i + 0] = pack2(q.x, q.x); w1[4 * i + 1] = pack2(q.y, q.y);
            w1[4 * i + 2] = pack2(q.z, q.z); w1[4 * i + 3] = pack2(q.w, q.w);
        }
        float bb = bl[v1]; b1 = pack2(bb, bb);
    } else {
#pragma unroll
        for (int e = 0; e < EMB; e++) w1[e] = 0ull;
    }
    __syncthreads();

#pragma unroll 2
    for (int rp = 0; rp < E_RT / 2; rp++) {
        unsigned long long acc0 = b0, acc1 = b1;
#pragma unroll
        for (int e = 0; e < EMB; e++) {
            unsigned long long o =
                *reinterpret_cast<const unsigned long long*>(s + e * E_RT + 2 * rp);
            asm("fma.rn.f32x2 %0, %1, %2, %0;" : "+l"(acc0) : "l"(o), "l"(w0[e]));
            asm("fma.rn.f32x2 %0, %1, %2, %0;" : "+l"(acc1) : "l"(o), "l"(w1[e]));
        }
        int r = rbase + 2 * rp;
        float lo, hi;
        if (ok0) {
            unpack2(acc0, lo, hi);
            out[(size_t)r * VOCAB + v0]       = lo;
            out[(size_t)(r + 1) * VOCAB + v0] = hi;
        }
        if (ok1) {
            unpack2(acc1, lo, hi);
            out[(size_t)r * VOCAB + v1]       = lo;
            out[(size_t)(r + 1) * VOCAB + v1] = hi;
        }
    }
}

// ---------------- launch ----------------
extern "C" void kernel_launch(void* const* d_in, const int* in_sizes, int n_in,
                              void* d_out, int out_size) {
    const int*   x   = (const int*)  d_in[0];
    const float* emb = (const float*)d_in[1];
    const float* Wq  = (const float*)d_in[2];
    const float* bq  = (const float*)d_in[3];
    const float* Wk  = (const float*)d_in[4];
    const float* bk  = (const float*)d_in[5];
    const float* Wv  = (const float*)d_in[6];
    const float* bv  = (const float*)d_in[7];
    const float* Wl  = (const float*)d_in[8];
    const float* bl  = (const float*)d_in[9];
    float* out = (float*)d_out;

    qkv_kernel<<<NROW / 256, 256>>>(x, emb, Wq, bq, Wk, bk, Wv, bv);

    dim3 gB(MCW / 16, MCW / 16, BS), bB(16, 16);
    scores_kernel<<<gB, bB>>>();

    softmax_kernel<<<NROW / 8, 256>>>();

    dim3 gD(MCW / 32, BS), bD(32, 8);
    attnout_kernel<<<gD, bD>>>();

    dim3 gE((VOCAB + 511) / 512, NROW / E_RT);
    logits_kernel<<<gE, 256>>>(Wl, bl, out);
}

// round 2
// speedup vs baseline: 1.1889x; 1.1889x over previous
#include <cuda_runtime.h>
#include <cuda_bf16.h>
#include <cstdint>

#define VOCAB 50257
#define EMB   16
#define BS    8
#define MCW   512
#define NROW  (BS * MCW)   // 4096
typedef unsigned long long ull;

// ---------------- scratch (static device globals; no allocs) ----------------
__device__ float g_q[NROW * EMB];
__device__ float g_k[NROW * EMB];
__device__ float g_v[NROW * EMB];
__device__ float g_sc[BS * MCW * MCW];     // TRANSPOSED scores: [b][k][q]  (8 MB)
__device__ float g_part[4 * EMB * NROW];   // attnout partials: [chunk][e][r]

__device__ __forceinline__ ull pack2(float lo, float hi) {
    ull r;
    asm("mov.b64 %0, {%1, %2};" : "=l"(r) : "f"(lo), "f"(hi));
    return r;
}
__device__ __forceinline__ void unpack2(ull p, float& lo, float& hi) {
    asm("mov.b64 {%0, %1}, %2;" : "=f"(lo), "=f"(hi) : "l"(p));
}

// ---------------- Kernel A: embeddings -> Q, K, V ----------------
__global__ void qkv_kernel(const int* __restrict__ x,
                           const float* __restrict__ emb_table,
                           const float* __restrict__ Wq, const float* __restrict__ bq,
                           const float* __restrict__ Wk, const float* __restrict__ bk,
                           const float* __restrict__ Wv, const float* __restrict__ bv) {
    __shared__ float sWq[EMB * EMB], sWk[EMB * EMB], sWv[EMB * EMB];
    __shared__ float sbq[EMB], sbk[EMB], sbv[EMB];
    int tid = threadIdx.x;
    if (tid < EMB * EMB) { sWq[tid] = Wq[tid]; sWk[tid] = Wk[tid]; sWv[tid] = Wv[tid]; }
    if (tid < EMB)       { sbq[tid] = bq[tid]; sbk[tid] = bk[tid]; sbv[tid] = bv[tid]; }
    __syncthreads();

    int t = blockIdx.x * blockDim.x + tid;   // 0..4095
    if (t >= NROW) return;
    int tok = x[t];

    float emb[EMB];
    const float4* ep = reinterpret_cast<const float4*>(emb_table + (size_t)tok * EMB);
#pragma unroll
    for (int i = 0; i < 4; i++) {
        float4 v4 = ep[i];
        emb[4 * i + 0] = v4.x; emb[4 * i + 1] = v4.y;
        emb[4 * i + 2] = v4.z; emb[4 * i + 3] = v4.w;
    }

#pragma unroll
    for (int i = 0; i < EMB; i++) {
        float aq = sbq[i], ak = sbk[i], av = sbv[i];
#pragma unroll
        for (int e = 0; e < EMB; e++) {
            aq += emb[e] * sWq[i * EMB + e];
            ak += emb[e] * sWk[i * EMB + e];
            av += emb[e] * sWv[i * EMB + e];
        }
        g_q[t * EMB + i] = aq;
        g_k[t * EMB + i] = ak;
        g_v[t * EMB + i] = av;
    }
}

// ---------------- Kernel B: scores (masked, zero->-inf), stored [b][k][q] ----------------
__global__ void scores_kernel() {
    __shared__ float sQ[16][17];
    __shared__ float sK[16][17];
    int b = blockIdx.z;
    int qbase = blockIdx.x * 16;
    int kbase = blockIdx.y * 16;
    int tx = threadIdx.x, ty = threadIdx.y;

    sQ[ty][tx] = g_q[((size_t)(b * MCW + qbase + ty)) * EMB + tx];
    sK[ty][tx] = g_k[((size_t)(b * MCW + kbase + ty)) * EMB + tx];
    __syncthreads();

    int q = qbase + tx;
    int k = kbase + ty;
    float dot = 0.f;
#pragma unroll
    for (int e = 0; e < EMB; e++) dot += sQ[tx][e] * sK[ty][e];

    float val = (k <= q) ? dot : 0.0f;
    if (val == 0.0f) val = __int_as_float(0xff800000);  // -inf
    g_sc[(size_t)b * MCW * MCW + (size_t)k * MCW + q] = val;
}

// ---------------- Kernel C: softmax over q (rows of transposed scores) ----------------
__global__ void softmax_kernel() {
    int warp = threadIdx.x >> 5, lane = threadIdx.x & 31;
    int row = blockIdx.x * 8 + warp;          // row = b*512 + k
    float* p = g_sc + (size_t)row * MCW;

    float v[16];
    float mx = -3.402823466e+38f;
#pragma unroll
    for (int j = 0; j < 16; j++) { v[j] = p[j * 32 + lane]; mx = fmaxf(mx, v[j]); }
#pragma unroll
    for (int s = 16; s > 0; s >>= 1) mx = fmaxf(mx, __shfl_xor_sync(0xffffffffu, mx, s));

    float sum = 0.f;
#pragma unroll
    for (int j = 0; j < 16; j++) { v[j] = expf(v[j] - mx); sum += v[j]; }
#pragma unroll
    for (int s = 16; s > 0; s >>= 1) sum += __shfl_xor_sync(0xffffffffu, sum, s);

    float inv = 1.0f / sum;
#pragma unroll
    for (int j = 0; j < 16; j++) p[j * 32 + lane] = v[j] * inv;
}

// ---------------- Kernel D: attnout partials, p split 4 ways ----------------
// grid (16 w-tiles, 8 b, 4 p-chunks), block (32, 8)
__global__ void attnout_kernel() {
    __shared__ float sV[128 * EMB];    // 8 KB  (V chunk)
    __shared__ float red[256 * EMB];   // 16 KB (reduction buffer)
    int b = blockIdx.y;
    int w0 = blockIdx.x * 32;
    int c  = blockIdx.z;
    int wl = threadIdx.x, pg = threadIdx.y;
    int tid = pg * 32 + wl;

    for (int i = tid; i < 128 * EMB; i += 256)
        sV[i] = g_v[(size_t)b * MCW * EMB + c * 128 * EMB + i];
    __syncthreads();

    float acc[EMB];
#pragma unroll
    for (int e = 0; e < EMB; e++) acc[e] = 0.f;

    const float* wbase = g_sc + (size_t)b * MCW * MCW + w0 + wl;
#pragma unroll
    for (int pi = 0; pi < 16; pi++) {
        int pl = pi * 8 + pg;               // local p within chunk
        float wgt = wbase[(size_t)(c * 128 + pl) * MCW];
#pragma unroll
        for (int e = 0; e < EMB; e++) acc[e] += wgt * sV[pl * EMB + e];
    }

#pragma unroll
    for (int e = 0; e < EMB; e++) red[tid * EMB + e] = acc[e];
    __syncthreads();

    if (pg == 0) {
#pragma unroll
        for (int e = 0; e < EMB; e++) {
            float s = 0.f;
#pragma unroll
            for (int g = 0; g < 8; g++) s += red[(g * 32 + wl) * EMB + e];
            g_part[(size_t)c * EMB * NROW + (size_t)e * NROW + b * MCW + w0 + wl] = s;
        }
    }
}

// ---------------- Kernel E: logits = out @ Wl.T + bl  (823 MB write) ----------------
// 128 threads/block, each thread owns 4 vocab ids (tid + j*128), f32x2 lanes
// paired over ROWS so weight splat-packs are loop-invariant registers.
#define E_RT 128
__global__ __launch_bounds__(128) void logits_kernel(const float* __restrict__ Wl,
                                                     const float* __restrict__ bl,
                                                     float* __restrict__ out) {
    __shared__ float s[EMB * E_RT];   // s[e][r_local], 8 KB
    int tid = threadIdx.x;
    int rbase = blockIdx.y * E_RT;

    // stage s tile = sum of the 4 attnout partials
    for (int i = tid; i < EMB * E_RT; i += 128) {
        int e = i >> 7, rl = i & (E_RT - 1);
        int idx = e * NROW + rbase + rl;
        s[i] = g_part[idx] + g_part[EMB * NROW + idx]
             + g_part[2 * EMB * NROW + idx] + g_part[3 * EMB * NROW + idx];
    }

    int  v[4];
    bool ok[4];
    ull  w[4][EMB], bb[4];
#pragma unroll
    for (int j = 0; j < 4; j++) {
        v[j] = blockIdx.x * 512 + tid + j * 128;
        ok[j] = (v[j] < VOCAB);
        if (ok[j]) {
            const float4* wp = reinterpret_cast<const float4*>(Wl + (size_t)v[j] * EMB);
#pragma unroll
            for (int i = 0; i < 4; i++) {
                float4 q = wp[i];
                w[j][4 * i + 0] = pack2(q.x, q.x); w[j][4 * i + 1] = pack2(q.y, q.y);
                w[j][4 * i + 2] = pack2(q.z, q.z); w[j][4 * i + 3] = pack2(q.w, q.w);
            }
            float b1 = bl[v[j]]; bb[j] = pack2(b1, b1);
        } else {
#pragma unroll
            for (int e = 0; e < EMB; e++) w[j][e] = 0ull;
            bb[j] = 0ull;
        }
    }
    __syncthreads();

#pragma unroll 2
    for (int rp = 0; rp < E_RT / 2; rp++) {
        ull acc0 = bb[0], acc1 = bb[1], acc2 = bb[2], acc3 = bb[3];
#pragma unroll
        for (int e = 0; e < EMB; e++) {
            ull o = *reinterpret_cast<const ull*>(s + e * E_RT + 2 * rp);
            asm("fma.rn.f32x2 %0, %1, %2, %0;" : "+l"(acc0) : "l"(o), "l"(w[0][e]));
            asm("fma.rn.f32x2 %0, %1, %2, %0;" : "+l"(acc1) : "l"(o), "l"(w[1][e]));
            asm("fma.rn.f32x2 %0, %1, %2, %0;" : "+l"(acc2) : "l"(o), "l"(w[2][e]));
            asm("fma.rn.f32x2 %0, %1, %2, %0;" : "+l"(acc3) : "l"(o), "l"(w[3][e]));
        }
        int r = rbase + 2 * rp;
        float lo, hi;
        ull accs[4] = {acc0, acc1, acc2, acc3};
#pragma unroll
        for (int j = 0; j < 4; j++) {
            if (ok[j]) {
                unpack2(accs[j], lo, hi);
                out[(size_t)r * VOCAB + v[j]]       = lo;
                out[(size_t)(r + 1) * VOCAB + v[j]] = hi;
            }
        }
    }
}

// ---------------- launch ----------------
extern "C" void kernel_launch(void* const* d_in, const int* in_sizes, int n_in,
                              void* d_out, int out_size) {
    const int*   x   = (const int*)  d_in[0];
    const float* emb = (const float*)d_in[1];
    const float* Wq  = (const float*)d_in[2];
    const float* bq  = (const float*)d_in[3];
    const float* Wk  = (const float*)d_in[4];
    const float* bk  = (const float*)d_in[5];
    const float* Wv  = (const float*)d_in[6];
    const float* bv  = (const float*)d_in[7];
    const float* Wl  = (const float*)d_in[8];
    const float* bl  = (const float*)d_in[9];
    float* out = (float*)d_out;

    qkv_kernel<<<NROW / 256, 256>>>(x, emb, Wq, bq, Wk, bk, Wv, bv);

    dim3 gB(MCW / 16, MCW / 16, BS), bB(16, 16);
    scores_kernel<<<gB, bB>>>();

    softmax_kernel<<<NROW / 8, 256>>>();

    dim3 gD(MCW / 32, BS, 4), bD(32, 8);
    attnout_kernel<<<gD, bD>>>();

    dim3 gE((VOCAB + 511) / 512, NROW / E_RT);
    logits_kernel<<<gE, 128>>>(Wl, bl, out);
}